// round 3
// baseline (speedup 1.0000x reference)
#include <cuda_runtime.h>
#include <cuda_bf16.h>
#include <math_constants.h>

#define N_NODES 3072
#define H_HEADS 8
#define DH 32
#define HID 256
#define DEG 16
#define EDIM 32
#define E_EDGES (N_NODES * DEG)
#define FFN 1024

// ---------------- scratch (no allocations allowed) ----------------
__device__ float g_Q[N_NODES * HID];
__device__ float g_K[N_NODES * HID];
__device__ float g_V[N_NODES * HID];
__device__ float g_eatt[E_EDGES * H_HEADS];
__device__ float g_att[N_NODES * HID];
__device__ float g_tmp[N_NODES * HID];
__device__ float g_x1[N_NODES * HID];
__device__ float g_ffh[N_NODES * FFN];
__device__ float g_tmp2[N_NODES * HID];

// ================= high-throughput fp32 GEMM =================
// C = A@B + bias (optional relu). A: M x Kin row-major, B: Kin x Nout row-major.
// Blocktile 128x64, BK=16, 256 threads, 8x4 per thread, float4 everywhere,
// register-prefetch double buffering (next tile's LDGs overlap current compute).
// Requires M%128==0, Nout%64==0, Kin%16==0 (all shapes here qualify).
template <int EPI>
__device__ __forceinline__ void gemm_body(
    const float* __restrict__ A, const float* __restrict__ B,
    const float* __restrict__ bias, float* __restrict__ C,
    int Kin, int Nout, int bm, int bn)
{
    constexpr int BM = 128, BN = 64, BK = 16, TM = 8, TN = 4;
    __shared__ float As[BK][BM + 4];   // +4 pad: conflict-free transposed stores
    __shared__ float Bs[BK][BN];

    const int tid = threadIdx.x;       // 0..255
    const int tx = tid & 15;           // 0..15 -> N
    const int ty = tid >> 4;           // 0..15 -> M

    // per-thread load coordinates (fixed across K-steps)
    const int ar0 = tid >> 2;                 // A rows for the 2 float4 loads
    const int ar1 = (tid + 256) >> 2;
    const int ac0 = (tid & 3) * 4;            // k-offset within tile
    const int ac1 = ac0;                      // (tid+256)&3 == tid&3
    const int br = tid >> 4;                  // B row in tile
    const int bc = (tid & 15) * 4;            // B col in tile

    float acc[TM][TN] = {};

    // prologue: load first tiles into registers
    float4 pa0 = *(const float4*)(A + (size_t)(bm + ar0) * Kin + ac0);
    float4 pa1 = *(const float4*)(A + (size_t)(bm + ar1) * Kin + ac1);
    float4 pb  = *(const float4*)(B + (size_t)br * Nout + bn + bc);

    for (int k0 = 0; k0 < Kin; k0 += BK) {
        // commit prefetched registers to smem (A transposed)
        As[ac0 + 0][ar0] = pa0.x; As[ac0 + 1][ar0] = pa0.y;
        As[ac0 + 2][ar0] = pa0.z; As[ac0 + 3][ar0] = pa0.w;
        As[ac1 + 0][ar1] = pa1.x; As[ac1 + 1][ar1] = pa1.y;
        As[ac1 + 2][ar1] = pa1.z; As[ac1 + 3][ar1] = pa1.w;
        *(float4*)&Bs[br][bc] = pb;
        __syncthreads();

        // issue next tile's loads early — latency hidden behind FFMA block
        const int kn = k0 + BK;
        if (kn < Kin) {
            pa0 = *(const float4*)(A + (size_t)(bm + ar0) * Kin + kn + ac0);
            pa1 = *(const float4*)(A + (size_t)(bm + ar1) * Kin + kn + ac1);
            pb  = *(const float4*)(B + (size_t)(kn + br) * Nout + bn + bc);
        }

        #pragma unroll
        for (int kk = 0; kk < BK; kk++) {
            float a[TM], b[TN];
            float4 a0 = *(const float4*)&As[kk][ty * TM];
            float4 a1 = *(const float4*)&As[kk][ty * TM + 4];
            a[0]=a0.x; a[1]=a0.y; a[2]=a0.z; a[3]=a0.w;
            a[4]=a1.x; a[5]=a1.y; a[6]=a1.z; a[7]=a1.w;
            float4 bv = *(const float4*)&Bs[kk][tx * TN];
            b[0]=bv.x; b[1]=bv.y; b[2]=bv.z; b[3]=bv.w;
            #pragma unroll
            for (int i = 0; i < TM; i++)
                #pragma unroll
                for (int j = 0; j < TN; j++)
                    acc[i][j] = fmaf(a[i], b[j], acc[i][j]);
        }
        __syncthreads();
    }

    // epilogue: float4 stores with bias (+relu)
    float4 bb = *(const float4*)(bias + bn + tx * TN);
    #pragma unroll
    for (int i = 0; i < TM; i++) {
        int row = bm + ty * TM + i;
        float4 v;
        v.x = acc[i][0] + bb.x;
        v.y = acc[i][1] + bb.y;
        v.z = acc[i][2] + bb.z;
        v.w = acc[i][3] + bb.w;
        if (EPI == 1) {
            v.x = fmaxf(v.x, 0.0f); v.y = fmaxf(v.y, 0.0f);
            v.z = fmaxf(v.z, 0.0f); v.w = fmaxf(v.w, 0.0f);
        }
        *(float4*)(C + (size_t)row * Nout + bn + tx * TN) = v;
    }
}

template <int EPI>
__global__ __launch_bounds__(256, 2) void gemm_bias(
    const float* __restrict__ A, const float* __restrict__ B,
    const float* __restrict__ bias, float* __restrict__ C,
    int Kin, int Nout)
{
    gemm_body<EPI>(A, B, bias, C, Kin, Nout, blockIdx.y * 128, blockIdx.x * 64);
}

// Fused QKV: gridDim.z selects which projection this block computes.
__global__ __launch_bounds__(256, 2) void qkv_gemm(
    const float* __restrict__ X,
    const float* __restrict__ Wq, const float* __restrict__ bq, float* __restrict__ Q,
    const float* __restrict__ Wk, const float* __restrict__ bk, float* __restrict__ K,
    const float* __restrict__ Wv, const float* __restrict__ bv, float* __restrict__ V)
{
    const float* W; const float* b; float* C;
    if (blockIdx.z == 0)      { W = Wq; b = bq; C = Q; }
    else if (blockIdx.z == 1) { W = Wk; b = bk; C = K; }
    else                      { W = Wv; b = bv; C = V; }
    gemm_body<0>(X, W, b, C, HID, HID, blockIdx.y * 128, blockIdx.x * 64);
}

// ---------------- edge attention bias: eatt = edge_features @ We + be ----------------
__global__ __launch_bounds__(256) void eatt_kernel(
    const float* __restrict__ ef, const float* __restrict__ We,
    const float* __restrict__ be, float* __restrict__ out)
{
    __shared__ float sWe[EDIM * H_HEADS];
    __shared__ float sbe[H_HEADS];
    int tid = threadIdx.x;
    if (tid < EDIM * H_HEADS) sWe[tid] = We[tid];
    if (tid < H_HEADS) sbe[tid] = be[tid];
    __syncthreads();

    int idx = blockIdx.x * 256 + tid;      // e*H + h
    if (idx < E_EDGES * H_HEADS) {
        int e = idx / H_HEADS, h = idx % H_HEADS;
        float s = sbe[h];
        const float* row = ef + (size_t)e * EDIM;
        #pragma unroll
        for (int d = 0; d < EDIM; d++) s += row[d] * sWe[d * H_HEADS + h];
        out[idx] = s;
    }
}

// ---------------- sparse neighbor attention ----------------
// One block per node, one warp per head.
// Dense-reference semantics: duplicate neighbors collapse to ONE softmax entry,
// and the edge bias of the LAST occurrence (scatter .set order) wins.
__global__ __launch_bounds__(256) void attn_kernel(
    const float* __restrict__ Q, const float* __restrict__ K,
    const float* __restrict__ V, const int* __restrict__ neighbors,
    const float* __restrict__ eatt, float* __restrict__ out)
{
    const int n = blockIdx.x;
    const int h = threadIdx.x >> 5;        // warp id = head
    const int lane = threadIdx.x & 31;

    __shared__ int nb[DEG];
    __shared__ float qsh[H_HEADS][DH];

    if (threadIdx.x < DEG) nb[threadIdx.x] = neighbors[n * DEG + threadIdx.x];
    qsh[h][lane] = Q[(size_t)n * HID + h * DH + lane];
    __syncthreads();

    float score = -CUDART_INF_F;
    int src = 0;
    if (lane < DEG) {
        const int j = lane;
        src = nb[j];
        bool valid = true;                 // keep only LAST occurrence of src
        #pragma unroll
        for (int j2 = 0; j2 < DEG; j2++)
            if (j2 > j && nb[j2] == src) valid = false;
        if (valid) {
            float s = 0.0f;
            const float* krow = K + (size_t)src * HID + h * DH;
            #pragma unroll
            for (int d = 0; d < DH; d++) s += qsh[h][d] * krow[d];
            score = s * 0.17677669529663689f /* 1/sqrt(32) */
                  + eatt[(size_t)(n * DEG + j) * H_HEADS + h];
        }
    }

    // warp softmax over the <=16 valid lanes
    float m = score;
    #pragma unroll
    for (int o = 16; o > 0; o >>= 1) m = fmaxf(m, __shfl_xor_sync(0xffffffffu, m, o));
    float p = (score > -1e30f) ? expf(score - m) : 0.0f;
    float sum = p;
    #pragma unroll
    for (int o = 16; o > 0; o >>= 1) sum += __shfl_xor_sync(0xffffffffu, sum, o);
    p /= sum;

    // weighted sum of V rows; each lane owns one output dim d
    const int d = lane;
    float acc = 0.0f;
    #pragma unroll
    for (int j = 0; j < DEG; j++) {
        float pj = __shfl_sync(0xffffffffu, p, j);
        int   sj = __shfl_sync(0xffffffffu, src, j);
        if (pj > 0.0f) acc += pj * V[(size_t)sj * HID + h * DH + d];
    }
    out[(size_t)n * HID + h * DH + d] = acc;
}

// ---------------- residual add + LayerNorm (one block per row) ----------------
__global__ __launch_bounds__(HID) void add_ln_kernel(
    const float* __restrict__ y, const float* __restrict__ res,
    const float* __restrict__ g, const float* __restrict__ b,
    float* __restrict__ out)
{
    const int row = blockIdx.x;
    const int tid = threadIdx.x;
    float v = y[(size_t)row * HID + tid] + res[(size_t)row * HID + tid];

    __shared__ float red[8];
    float s = v;
    #pragma unroll
    for (int o = 16; o > 0; o >>= 1) s += __shfl_xor_sync(0xffffffffu, s, o);
    if ((tid & 31) == 0) red[tid >> 5] = s;
    __syncthreads();
    float mu = 0.0f;
    #pragma unroll
    for (int i = 0; i < 8; i++) mu += red[i];
    mu *= (1.0f / HID);

    float d = v - mu;
    float s2 = d * d;
    #pragma unroll
    for (int o = 16; o > 0; o >>= 1) s2 += __shfl_xor_sync(0xffffffffu, s2, o);
    __syncthreads();
    if ((tid & 31) == 0) red[tid >> 5] = s2;
    __syncthreads();
    float var = 0.0f;
    #pragma unroll
    for (int i = 0; i < 8; i++) var += red[i];
    var *= (1.0f / HID);

    out[(size_t)row * HID + tid] = d * rsqrtf(var + 1e-5f) * g[tid] + b[tid];
}

// ---------------- host launcher ----------------
extern "C" void kernel_launch(void* const* d_in, const int* in_sizes, int n_in,
                              void* d_out, int out_size)
{
    const float* node_states = (const float*)d_in[0];
    const int*   neighbors   = (const int*)  d_in[1];
    const float* edge_feats  = (const float*)d_in[2];
    const float* Wq  = (const float*)d_in[3];
    const float* bq  = (const float*)d_in[4];
    const float* Wk  = (const float*)d_in[5];
    const float* bk  = (const float*)d_in[6];
    const float* Wv  = (const float*)d_in[7];
    const float* bv  = (const float*)d_in[8];
    const float* We  = (const float*)d_in[9];
    const float* be  = (const float*)d_in[10];
    const float* Wo  = (const float*)d_in[11];
    const float* bo  = (const float*)d_in[12];
    const float* ln1g = (const float*)d_in[13];
    const float* ln1b = (const float*)d_in[14];
    const float* ln2g = (const float*)d_in[15];
    const float* ln2b = (const float*)d_in[16];
    const float* Wf1 = (const float*)d_in[17];
    const float* bf1 = (const float*)d_in[18];
    const float* Wf2 = (const float*)d_in[19];
    const float* bf2 = (const float*)d_in[20];
    float* out = (float*)d_out;

    float *pQ, *pK, *pV, *pE, *pA, *pT, *pX1, *pF, *pT2;
    cudaGetSymbolAddress((void**)&pQ,  g_Q);
    cudaGetSymbolAddress((void**)&pK,  g_K);
    cudaGetSymbolAddress((void**)&pV,  g_V);
    cudaGetSymbolAddress((void**)&pE,  g_eatt);
    cudaGetSymbolAddress((void**)&pA,  g_att);
    cudaGetSymbolAddress((void**)&pT,  g_tmp);
    cudaGetSymbolAddress((void**)&pX1, g_x1);
    cudaGetSymbolAddress((void**)&pF,  g_ffh);
    cudaGetSymbolAddress((void**)&pT2, g_tmp2);

    dim3 blk(256);
    dim3 grid_qkv(HID / 64, N_NODES / 128, 3);   // (4, 24, 3)
    dim3 grid_h(HID / 64, N_NODES / 128);        // (4, 24)
    dim3 grid_f1(FFN / 64, N_NODES / 128);       // (16, 24)

    // fused QKV projections (one launch, 288 blocks)
    qkv_gemm<<<grid_qkv, blk>>>(node_states, Wq, bq, pQ, Wk, bk, pK, Wv, bv, pV);

    // edge attention bias
    eatt_kernel<<<(E_EDGES * H_HEADS + 255) / 256, blk>>>(edge_feats, We, be, pE);

    // sparse neighbor attention
    attn_kernel<<<N_NODES, blk>>>(pQ, pK, pV, neighbors, pE, pA);

    // output projection + residual LN
    gemm_bias<0><<<grid_h, blk>>>(pA, Wo, bo, pT, HID, HID);
    add_ln_kernel<<<N_NODES, HID>>>(pT, node_states, ln1g, ln1b, pX1);

    // FFN
    gemm_bias<1><<<grid_f1, blk>>>(pX1, Wf1, bf1, pF, HID, FFN);
    gemm_bias<0><<<grid_h, blk>>>(pF, Wf2, bf2, pT2, FFN, HID);
    add_ln_kernel<<<N_NODES, HID>>>(pT2, pX1, ln2g, ln2b, out);
}